// round 8
// baseline (speedup 1.0000x reference)
#include <cuda_runtime.h>
#include <math.h>
#include <stdint.h>

#define TT 512
#define BB 64
#define HH 1024
#define NCTA 128
#define NTHR 256
#define CK 128   // k-rows per staged chunk (32KB)

typedef unsigned long long u64;

__device__ __align__(256) float g_xT[(size_t)TT * HH * BB];  // [t][k][b]
__device__ __align__(256) float g_h0[2][HH * BB];            // [k][b]; H0[t] in g_h0[t&1]
__device__ __align__(256) float g_h1[2][HH * BB];            // H1[t] in g_h1[t&1]
__device__ u64 g_arrive;
__device__ volatile u64 g_release;

__device__ __forceinline__ void ffma2(u64& d, u64 a, u64 b)
{ asm("fma.rn.f32x2 %0,%1,%2,%0;" : "+l"(d) : "l"(a), "l"(b)); }
__device__ __forceinline__ void fadd2(u64& d, u64 a)
{ asm("add.rn.f32x2 %0,%0,%1;" : "+l"(d) : "l"(a)); }
__device__ __forceinline__ u64 dup2(float x)
{ u64 r; asm("mov.b64 %0,{%1,%1};" : "=l"(r) : "f"(x)); return r; }
__device__ __forceinline__ void unpack2(u64 s, float& lo, float& hi)
{ asm("mov.b64 {%0,%1},%2;" : "=f"(lo), "=f"(hi) : "l"(s)); }

// Split ticket barrier (monotonic across graph replays; 1 CTA/SM, all resident)
__device__ __forceinline__ void bar_arrive(u64& tkt)
{
    __syncthreads();
    if (threadIdx.x == 0) {
        __threadfence();
        u64 old = atomicAdd(&g_arrive, 1ULL);
        tkt = old / NCTA + 1ULL;
        if ((old % NCTA) == (NCTA - 1)) { __threadfence(); g_release = tkt; }
    }
}
__device__ __forceinline__ void bar_wait(u64 tkt)
{
    if (threadIdx.x == 0) {
        while (g_release < tkt) {}
        __threadfence();
    }
    __syncthreads();
}

// cp.async one 32KB chunk (CK k x 64 b floats), L2 path (.cg) for coherence.
__device__ __forceinline__ void cp_chunk(float* sbuf, const float* gsrc)
{
    uint32_t s = (uint32_t)__cvta_generic_to_shared(sbuf) + threadIdx.x * 16;
    const char* g = (const char*)gsrc + threadIdx.x * 16;
#pragma unroll
    for (int i = 0; i < 8; i++)
        asm volatile("cp.async.cg.shared.global [%0],[%1],16;" :: "r"(s + i * 4096), "l"(g + i * 4096));
    asm volatile("cp.async.commit_group;");
}
__device__ __forceinline__ void cp_wait_all()
{ asm volatile("cp.async.wait_group 0;" ::: "memory"); }

// ---------------------------------------------------------------------------
// compute_chunk: lane owns 8 j (4 j-pairs) x 4 b. CK=128 rows, 8 iters,
// half-warp k2 handles rows kb, kb+2, ... Weights broadcast (16B/half-warp).
// wA/wB point at this chunk's [CK][8] weight rows.
// ---------------------------------------------------------------------------
template<int NW>
__device__ __forceinline__ void compute_chunk(const float* __restrict__ buf,
                                              const float* __restrict__ wA,
                                              const float* __restrict__ wB,
                                              u64 (&aA)[4][4], u64 (&aB)[4][4],
                                              int kb, int b0)
{
#pragma unroll
    for (int i = 0; i < 8; i++) {
        int kl = kb + 2 * i;
        float4 h4 = *(const float4*)(buf + kl * 64 + b0);
        u64 hd0 = dup2(h4.x), hd1 = dup2(h4.y), hd2 = dup2(h4.z), hd3 = dup2(h4.w);
        ulonglong2 wa0 = *(const ulonglong2*)(wA + (size_t)kl * 8);
        ulonglong2 wa1 = *(const ulonglong2*)(wA + (size_t)kl * 8 + 4);
        ffma2(aA[0][0], wa0.x, hd0); ffma2(aA[0][1], wa0.x, hd1);
        ffma2(aA[0][2], wa0.x, hd2); ffma2(aA[0][3], wa0.x, hd3);
        ffma2(aA[1][0], wa0.y, hd0); ffma2(aA[1][1], wa0.y, hd1);
        ffma2(aA[1][2], wa0.y, hd2); ffma2(aA[1][3], wa0.y, hd3);
        ffma2(aA[2][0], wa1.x, hd0); ffma2(aA[2][1], wa1.x, hd1);
        ffma2(aA[2][2], wa1.x, hd2); ffma2(aA[2][3], wa1.x, hd3);
        ffma2(aA[3][0], wa1.y, hd0); ffma2(aA[3][1], wa1.y, hd1);
        ffma2(aA[3][2], wa1.y, hd2); ffma2(aA[3][3], wa1.y, hd3);
        if (NW == 2) {
            ulonglong2 wb0 = *(const ulonglong2*)(wB + (size_t)kl * 8);
            ulonglong2 wb1 = *(const ulonglong2*)(wB + (size_t)kl * 8 + 4);
            ffma2(aB[0][0], wb0.x, hd0); ffma2(aB[0][1], wb0.x, hd1);
            ffma2(aB[0][2], wb0.x, hd2); ffma2(aB[0][3], wb0.x, hd3);
            ffma2(aB[1][0], wb0.y, hd0); ffma2(aB[1][1], wb0.y, hd1);
            ffma2(aB[1][2], wb0.y, hd2); ffma2(aB[1][3], wb0.y, hd3);
            ffma2(aB[2][0], wb1.x, hd0); ffma2(aB[2][1], wb1.x, hd1);
            ffma2(aB[2][2], wb1.x, hd2); ffma2(aB[2][3], wb1.x, hd3);
            ffma2(aB[3][0], wb1.y, hd0); ffma2(aB[3][1], wb1.y, hd1);
            ffma2(aB[3][2], wb1.y, hd2); ffma2(aB[3][3], wb1.y, hd3);
        }
    }
}

__device__ __forceinline__ void stred(u64* r64, u64 (&a)[4][4], int gr, int b0)
{
#pragma unroll
    for (int jp = 0; jp < 4; jp++) {
        ulonglong2 v0; v0.x = a[jp][0]; v0.y = a[jp][1];
        ulonglong2 v1; v1.x = a[jp][2]; v1.y = a[jp][3];
        *(ulonglong2*)&r64[(gr * 4 + jp) * 64 + b0] = v0;
        *(ulonglong2*)&r64[(gr * 4 + jp) * 64 + b0 + 2] = v1;
    }
}

__device__ __forceinline__ u64 gather16(const u64* r64, int jp, int b)
{
    u64 s0 = r64[(0 * 4 + jp) * 64 + b];
    u64 s1 = r64[(1 * 4 + jp) * 64 + b];
#pragma unroll
    for (int gr = 2; gr < 16; gr += 2) {
        fadd2(s0, r64[(gr * 4 + jp) * 64 + b]);
        fadd2(s1, r64[((gr + 1) * 4 + jp) * 64 + b]);
    }
    fadd2(s0, s1);
    return s0;
}

#define ZERO44(A) do { _Pragma("unroll") for (int _j = 0; _j < 4; _j++) \
    _Pragma("unroll") for (int _b = 0; _b < 4; _b++) (A)[_j][_b] = 0ULL; } while (0)

// ---------------------------------------------------------------------------
// Persistent kernel. 128 CTAs x 256 thr; CTA owns j [8*bid, 8*bid+8).
// SMEM floats: wt1[0,8K) Wih1 | wt0[8K,16K) Whh0 | wt2[16K,24K) Whh1 |
//   wtx[24K,32K) Wih0 | buf0[32K,40K) | buf1[40K,48K) | ring[48K,+1024) |
//   bias1[49216,+8) | biasx[49224,+8)      (offsets in floats; 200,768 B)
// red regions alias buf0 (accA/accC) and buf1 (accB).
// ---------------------------------------------------------------------------
__global__ void __launch_bounds__(NTHR, 1) rnn_persist(
    const float* __restrict__ X, const float* __restrict__ h0in,
    const float* __restrict__ Wih0, const float* __restrict__ bih0,
    const float* __restrict__ Whh0, const float* __restrict__ bhh0,
    const float* __restrict__ Wih1, const float* __restrict__ bih1,
    const float* __restrict__ Whh1, const float* __restrict__ bhh1,
    float* __restrict__ out)
{
    extern __shared__ float sm[];
    float* wt1  = sm;
    float* wt0  = sm + 8192;
    float* wt2  = sm + 16384;
    float* wtx  = sm + 24576;
    float* buf0 = sm + 32768;
    float* buf1 = sm + 40960;
    float* ring = sm + 49152;    // 2 slots x 8 j x 64 b
    float* bias1 = sm + 50176;
    float* biasx = sm + 50184;
    u64* redA = (u64*)buf0;
    u64* redB = (u64*)buf1;

    const int tid = threadIdx.x;
    const int lane = tid & 31;
    const int g = tid >> 5;
    const int k2 = lane >> 4;
    const int b0 = (lane & 15) * 4;
    const int kb = g * 16 + k2;
    const int gr = g * 2 + k2;
    const int jbase = blockIdx.x * 8;
    const int ejp = tid & 3, eb = tid >> 2;
    u64 tkt = 0;

    // --- prologue: weights (natural [k][8]) + biases ---
    for (int idx = tid; idx < 8192; idx += NTHR) {
        int jj = idx >> 10, k = idx & 1023;
        wt0[k * 8 + jj] = __ldg(&Whh0[(size_t)(jbase + jj) * 1024 + k]);
        wt1[k * 8 + jj] = __ldg(&Wih1[(size_t)(jbase + jj) * 1024 + k]);
        wt2[k * 8 + jj] = __ldg(&Whh1[(size_t)(jbase + jj) * 1024 + k]);
        wtx[k * 8 + jj] = __ldg(&Wih0[(size_t)(jbase + jj) * 1024 + k]);
    }
    if (tid < 8) {
        bias1[tid] = __ldg(&bih1[jbase + tid]) + __ldg(&bhh1[jbase + tid]);
        biasx[tid] = __ldg(&bih0[jbase + tid]) + __ldg(&bhh0[jbase + tid]);
    }

    // --- prologue: transpose h_0 slice ([2][b][k] -> [k][b]) ---
#pragma unroll
    for (int i = 0; i < 4; i++) {
        int idx = tid + i * NTHR;
        int l = idx >> 9, r = idx & 511, k = jbase + (r >> 6), b = r & 63;
        float v = __ldg(&h0in[(size_t)l * 65536 + (size_t)b * 1024 + k]);
        float* dst = l ? g_h1[1] : g_h0[1];
        __stcg(&dst[k * 64 + b], v);
    }

    // --- prologue: transpose x -> g_xT ([t][b][k] -> [t][k][b]), 4 t/CTA ---
    {
        float* tr = buf0;  // 64 x 132 staging spans buf0..buf1
        for (int s = 0; s < 4; s++) {
            int t = blockIdx.x * 4 + s;
            const float* xs = X + (size_t)t * 65536;
            float* xd = g_xT + (size_t)t * 65536;
            for (int kc = 0; kc < 8; kc++) {
                __syncthreads();
#pragma unroll
                for (int i = 0; i < 8; i++) {
                    int q = tid + i * 256;
                    int b = q >> 5, k4 = (q & 31) * 4;
                    float4 v = __ldg((const float4*)&xs[(size_t)b * 1024 + kc * 128 + k4]);
                    *(float4*)&tr[b * 132 + k4] = v;
                }
                __syncthreads();
#pragma unroll
                for (int i = 0; i < 8; i++) {
                    int q = tid + i * 256;
                    int k = q >> 4, b4 = (q & 15) * 4;
                    float4 v = make_float4(tr[(b4 + 0) * 132 + k], tr[(b4 + 1) * 132 + k],
                                           tr[(b4 + 2) * 132 + k], tr[(b4 + 3) * 132 + k]);
                    __stcg((float4*)&xd[(size_t)(kc * 128 + k) * 64 + b4], v);
                }
            }
        }
    }
    bar_arrive(tkt);
    bar_wait(tkt);   // xT + transposed h_0 globally visible

    u64 aA[4][4], aB[4][4];

    // --- prologue: pre[0] -> ring slot 0, pre[1] -> ring slot 1 ---
#pragma unroll
    for (int s = 0; s < 2; s++) {
        ZERO44(aB);
        const float* xs = g_xT + (size_t)s * 65536;
        cp_chunk(buf0, xs);
        for (int c = 0; c < 8; c++) {
            cp_wait_all();
            __syncthreads();
            if (c < 7) cp_chunk((c & 1) ? buf0 : buf1, xs + (size_t)(c + 1) * CK * 64);
            compute_chunk<1>((c & 1) ? buf1 : buf0, wtx + (size_t)c * CK * 8, wtx, aB, aA, kb, b0);
        }
        stred(redA, aB, gr, b0);   // redA = buf0: safe, last compute read buf1
        __syncthreads();
        {
            u64 v = gather16(redA, ejp, eb);
            float lo, hi; unpack2(v, lo, hi);
            ring[s * 512 + (ejp * 2) * 64 + eb] = lo + biasx[ejp * 2];
            ring[s * 512 + (ejp * 2 + 1) * 64 + eb] = hi + biasx[ejp * 2 + 1];
        }
        __syncthreads();
    }

    // --- prologue: H0[0] = tanh(pre[0] + Whh0·H0[-1]) ---
    ZERO44(aB);
    cp_chunk(buf0, g_h0[1]);
    for (int c = 0; c < 8; c++) {
        cp_wait_all();
        __syncthreads();
        if (c < 7) cp_chunk((c & 1) ? buf0 : buf1, g_h0[1] + (size_t)(c + 1) * CK * 64);
        compute_chunk<1>((c & 1) ? buf1 : buf0, wt0 + (size_t)c * CK * 8, wt0, aB, aA, kb, b0);
    }
    stred(redA, aB, gr, b0);
    __syncthreads();
    {
        u64 v = gather16(redA, ejp, eb);
        float lo, hi; unpack2(v, lo, hi);
        int j = jbase + ejp * 2;
        __stcg(&g_h0[0][j * 64 + eb], tanhf(lo + ring[(ejp * 2) * 64 + eb]));
        __stcg(&g_h0[0][(j + 1) * 64 + eb], tanhf(hi + ring[(ejp * 2 + 1) * 64 + eb]));
    }
    bar_arrive(tkt);

    // --- main loop: interval t computes pre[t+2], H1[t], H0[t+1] ---
    for (int t = 0; t < TT; t++) {
        const int p = t & 1;

        // x-pass (independent work hides barrier latency); result -> ring[t&1]
        if (t < TT - 2) {
            ZERO44(aB);
            const float* xs = g_xT + (size_t)(t + 2) * 65536;
            cp_chunk(buf0, xs);
            for (int c = 0; c < 8; c++) {
                cp_wait_all();
                __syncthreads();
                if (c < 7) cp_chunk((c & 1) ? buf0 : buf1, xs + (size_t)(c + 1) * CK * 64);
                compute_chunk<1>((c & 1) ? buf1 : buf0, wtx + (size_t)c * CK * 8, wtx, aB, aA, kb, b0);
            }
            stred(redA, aB, gr, b0);
            __syncthreads();
            u64 v = gather16(redA, ejp, eb);
            float lo, hi; unpack2(v, lo, hi);
            ring[p * 512 + (ejp * 2) * 64 + eb] = lo + biasx[ejp * 2];
            ring[p * 512 + (ejp * 2 + 1) * 64 + eb] = hi + biasx[ejp * 2 + 1];
        }

        bar_wait(tkt);   // H0[t], H1[t-1] from all CTAs now visible

        ZERO44(aA); ZERO44(aB);
        const float* h0src = g_h0[p];
        const float* h1src = g_h1[p ^ 1];
        cp_chunk(buf0, h0src);
        for (int c = 0; c < 16; c++) {
            cp_wait_all();
            __syncthreads();
            if (c < 15) {
                const float* nsrc = (c + 1 < 8) ? (h0src + (size_t)(c + 1) * CK * 64)
                                                : (h1src + (size_t)(c + 1 - 8) * CK * 64);
                cp_chunk((c & 1) ? buf0 : buf1, nsrc);
            }
            const float* cbuf = (c & 1) ? buf1 : buf0;
            if (c < 8)
                compute_chunk<2>(cbuf, wt1 + (size_t)c * CK * 8, wt0 + (size_t)c * CK * 8,
                                 aA, aB, kb, b0);
            else
                compute_chunk<1>(cbuf, wt2 + (size_t)(c - 8) * CK * 8, wt2, aA, aB, kb, b0);
        }

        // reductions: aA -> redA(buf0) safe now (last compute read buf1);
        // aB -> redB(buf1) needs all computes done first.
        stred(redA, aA, gr, b0);
        __syncthreads();
        stred(redB, aB, gr, b0);
        __syncthreads();

        // epilogue A: H0[t+1] = tanh(accB + pre[t+1])
        if (t < TT - 1) {
            u64 v = gather16(redB, ejp, eb);
            float lo, hi; unpack2(v, lo, hi);
            int j = jbase + ejp * 2;
            const float* pp = ring + ((t + 1) & 1) * 512 + (ejp * 2) * 64 + eb;
            __stcg(&g_h0[p ^ 1][j * 64 + eb], tanhf(lo + pp[0]));
            __stcg(&g_h0[p ^ 1][(j + 1) * 64 + eb], tanhf(hi + pp[64]));
        }
        // epilogue B: H1[t] = tanh(accA + bias1); write outputs[t]
        {
            u64 v = gather16(redA, ejp, eb);
            float lo, hi; unpack2(v, lo, hi);
            int j = jbase + ejp * 2;
            float v0 = tanhf(lo + bias1[ejp * 2]);
            float v1 = tanhf(hi + bias1[ejp * 2 + 1]);
            __stcg(&g_h1[p][j * 64 + eb], v0);
            __stcg(&g_h1[p][(j + 1) * 64 + eb], v1);
            float2 ov; ov.x = v0; ov.y = v1;
            *(float2*)&out[(size_t)t * 65536 + (size_t)eb * 1024 + j] = ov;
        }
        bar_arrive(tkt);
    }
    bar_wait(tkt);   // all CTAs' final states visible

    // h_n: H0[511] in g_h0[1], H1[511] in g_h1[1]
    for (int e = blockIdx.x * NTHR + tid; e < 2 * BB * HH; e += NCTA * NTHR) {
        int l = e >> 16, r = e & 65535, b = r >> 10, k = r & 1023;
        const float* src = l ? g_h1[1] : g_h0[1];
        out[(size_t)TT * BB * HH + e] = __ldcg(&src[k * 64 + b]);
    }
}

// ---------------------------------------------------------------------------
extern "C" void kernel_launch(void* const* d_in, const int* in_sizes, int n_in,
                              void* d_out, int out_size)
{
    const float* input = (const float*)d_in[0];
    const float* h0in  = (const float*)d_in[1];
    const float* Wih0  = (const float*)d_in[2];
    const float* bih0  = (const float*)d_in[3];
    const float* Whh0  = (const float*)d_in[4];
    const float* bhh0  = (const float*)d_in[5];
    const float* Wih1  = (const float*)d_in[6];
    const float* bih1  = (const float*)d_in[7];
    const float* Whh1  = (const float*)d_in[8];
    const float* bhh1  = (const float*)d_in[9];
    float* out = (float*)d_out;

    const int smem_bytes = 50192 * 4;  // 200,768 B
    cudaFuncSetAttribute(rnn_persist, cudaFuncAttributeMaxDynamicSharedMemorySize, smem_bytes);

    rnn_persist<<<NCTA, NTHR, smem_bytes>>>(input, h0in, Wih0, bih0, Whh0, bhh0,
                                            Wih1, bih1, Whh1, bhh1, out);
}

// round 9
// speedup vs baseline: 1.0883x; 1.0883x over previous
#include <cuda_runtime.h>
#include <math.h>
#include <stdint.h>

#define TT 512
#define BB 64
#define HH 1024
#define NCTA 128
#define NTHR 512
#define CK 256   // k-rows per staged chunk (64KB)

typedef unsigned long long u64;

__device__ __align__(256) float g_pre[(size_t)TT * HH * BB];  // [t][j][b]
__device__ __align__(256) float g_h0[2][HH * BB];             // [k][b]; H0[t] in g_h0[t&1]
__device__ __align__(256) float g_h1[2][HH * BB];             // H1[t] in g_h1[t&1]
__device__ u64 g_arrive;
__device__ volatile u64 g_release;

__device__ __forceinline__ void ffma2(u64& d, u64 a, u64 b)
{ asm("fma.rn.f32x2 %0,%1,%2,%0;" : "+l"(d) : "l"(a), "l"(b)); }
__device__ __forceinline__ void fadd2(u64& d, u64 a)
{ asm("add.rn.f32x2 %0,%0,%1;" : "+l"(d) : "l"(a)); }
__device__ __forceinline__ u64 dup2(float x)
{ u64 r; asm("mov.b64 %0,{%1,%1};" : "=l"(r) : "f"(x)); return r; }
__device__ __forceinline__ void unpack2(u64 s, float& lo, float& hi)
{ asm("mov.b64 {%0,%1},%2;" : "=f"(lo), "=f"(hi) : "l"(s)); }

// Split ticket barrier (monotonic across graph replays; 1 CTA/SM, all resident)
__device__ __forceinline__ void bar_arrive(u64& tkt)
{
    __syncthreads();
    if (threadIdx.x == 0) {
        __threadfence();
        u64 old = atomicAdd(&g_arrive, 1ULL);
        tkt = old / NCTA + 1ULL;
        if ((old % NCTA) == (NCTA - 1)) { __threadfence(); g_release = tkt; }
    }
}
__device__ __forceinline__ void bar_wait(u64 tkt)
{
    if (threadIdx.x == 0) {
        while (g_release < tkt) {}
        __threadfence();
    }
    __syncthreads();
}

// cp.async one 64KB chunk (CK k x 64 b floats), L2 path (.cg) for coherence.
// 512 threads x 128B each.
__device__ __forceinline__ void cp_chunk(float* sbuf, const float* gsrc)
{
    uint32_t s = (uint32_t)__cvta_generic_to_shared(sbuf) + threadIdx.x * 16;
    const char* g = (const char*)gsrc + threadIdx.x * 16;
#pragma unroll
    for (int i = 0; i < 8; i++)
        asm volatile("cp.async.cg.shared.global [%0],[%1],16;" :: "r"(s + i * 8192), "l"(g + i * 8192));
    asm volatile("cp.async.commit_group;");
}
__device__ __forceinline__ void cp_wait_all()
{ asm volatile("cp.async.wait_group 0;" ::: "memory"); }

// ---------------------------------------------------------------------------
// pregemm (FFMA2): g_pre[t][j][b] = x[t][b]·Wih0[j] + bih0[j] + bhh0[j]
// 128x64 tile, 256 thr; per-thread 4 m-pairs x 4 n, packed over m.
// ---------------------------------------------------------------------------
__global__ void __launch_bounds__(256) pregemm(const float* __restrict__ X,
                                               const float* __restrict__ W,
                                               const float* __restrict__ bih,
                                               const float* __restrict__ bhh)
{
    __shared__ float As[16][132];  // [k][m]
    __shared__ float Bs[16][68];   // [k][n]
    const int tid = threadIdx.x;
    const int m0 = blockIdx.y * 128;
    const int n0 = blockIdx.x * 64;
    const int tx = tid & 15;
    const int ty = tid >> 4;

    u64 acc[4][4];
#pragma unroll
    for (int i = 0; i < 4; i++)
#pragma unroll
        for (int j = 0; j < 4; j++) acc[i][j] = 0ULL;

    for (int k0 = 0; k0 < 1024; k0 += 16) {
#pragma unroll
        for (int i = 0; i < 2; i++) {
            int q = tid + i * 256;
            int m = q >> 2, kq = (q & 3) << 2;
            float4 v = __ldg((const float4*)&X[(size_t)(m0 + m) * 1024 + k0 + kq]);
            As[kq + 0][m] = v.x; As[kq + 1][m] = v.y;
            As[kq + 2][m] = v.z; As[kq + 3][m] = v.w;
        }
        {
            int n = tid >> 2, kq = (tid & 3) << 2;
            float4 v = __ldg((const float4*)&W[(size_t)(n0 + n) * 1024 + k0 + kq]);
            Bs[kq + 0][n] = v.x; Bs[kq + 1][n] = v.y;
            Bs[kq + 2][n] = v.z; Bs[kq + 3][n] = v.w;
        }
        __syncthreads();
#pragma unroll
        for (int kk = 0; kk < 16; kk++) {
            ulonglong2 a01 = *(const ulonglong2*)&As[kk][ty * 8];
            ulonglong2 a23 = *(const ulonglong2*)&As[kk][ty * 8 + 4];
            float4 bv = *(const float4*)&Bs[kk][tx * 4];
            u64 bd0 = dup2(bv.x), bd1 = dup2(bv.y), bd2 = dup2(bv.z), bd3 = dup2(bv.w);
            ffma2(acc[0][0], a01.x, bd0); ffma2(acc[0][1], a01.x, bd1);
            ffma2(acc[0][2], a01.x, bd2); ffma2(acc[0][3], a01.x, bd3);
            ffma2(acc[1][0], a01.y, bd0); ffma2(acc[1][1], a01.y, bd1);
            ffma2(acc[1][2], a01.y, bd2); ffma2(acc[1][3], a01.y, bd3);
            ffma2(acc[2][0], a23.x, bd0); ffma2(acc[2][1], a23.x, bd1);
            ffma2(acc[2][2], a23.x, bd2); ffma2(acc[2][3], a23.x, bd3);
            ffma2(acc[3][0], a23.y, bd0); ffma2(acc[3][1], a23.y, bd1);
            ffma2(acc[3][2], a23.y, bd2); ffma2(acc[3][3], a23.y, bd3);
        }
        __syncthreads();
    }

#pragma unroll
    for (int ip = 0; ip < 4; ip++) {
        int m = m0 + ty * 8 + 2 * ip;     // pair (m, m+1): same t, consecutive b
        int t = m >> 6, b = m & 63;
#pragma unroll
        for (int j = 0; j < 4; j++) {
            int gn = n0 + tx * 4 + j;
            u64 bias = dup2(__ldg(&bih[gn]) + __ldg(&bhh[gn]));
            fadd2(acc[ip][j], bias);
            *(u64*)&g_pre[((size_t)t * 1024 + gn) * 64 + b] = acc[ip][j];
        }
    }
}

// ---------------------------------------------------------------------------
// compute_chunk: thread owns 8 j (4 natural weight pairs) x 2 b.
// CK=256 rows per chunk, 16 granules, 16 rows per granule per chunk.
// h: LDS.64 natural (b,b+1) -> unpack + 2 dup. Weights: 2x LDS.128 broadcast.
// ---------------------------------------------------------------------------
template<int NW>
__device__ __forceinline__ void compute_chunk(const float* __restrict__ buf,
                                              const float* __restrict__ wA,
                                              const float* __restrict__ wB,
                                              u64 (&aA)[4][2], u64 (&aB)[4][2],
                                              int kb, int b0)
{
#pragma unroll
    for (int i = 0; i < 16; i++) {
        int kl = kb + i;
        u64 hp = *(const u64*)(buf + kl * 64 + b0);
        float f0, f1; unpack2(hp, f0, f1);
        u64 hd0 = dup2(f0), hd1 = dup2(f1);
        ulonglong2 wa0 = *(const ulonglong2*)(wA + (size_t)kl * 8);
        ulonglong2 wa1 = *(const ulonglong2*)(wA + (size_t)kl * 8 + 4);
        ffma2(aA[0][0], wa0.x, hd0); ffma2(aA[0][1], wa0.x, hd1);
        ffma2(aA[1][0], wa0.y, hd0); ffma2(aA[1][1], wa0.y, hd1);
        ffma2(aA[2][0], wa1.x, hd0); ffma2(aA[2][1], wa1.x, hd1);
        ffma2(aA[3][0], wa1.y, hd0); ffma2(aA[3][1], wa1.y, hd1);
        if (NW == 2) {
            ulonglong2 wb0 = *(const ulonglong2*)(wB + (size_t)kl * 8);
            ulonglong2 wb1 = *(const ulonglong2*)(wB + (size_t)kl * 8 + 4);
            ffma2(aB[0][0], wb0.x, hd0); ffma2(aB[0][1], wb0.x, hd1);
            ffma2(aB[1][0], wb0.y, hd0); ffma2(aB[1][1], wb0.y, hd1);
            ffma2(aB[2][0], wb1.x, hd0); ffma2(aB[2][1], wb1.x, hd1);
            ffma2(aB[3][0], wb1.y, hd0); ffma2(aB[3][1], wb1.y, hd1);
        }
    }
}

__device__ __forceinline__ void stred(u64* r64, u64 (&a)[4][2], int gr, int b0)
{
#pragma unroll
    for (int jp = 0; jp < 4; jp++) {
        ulonglong2 v; v.x = a[jp][0]; v.y = a[jp][1];
        *(ulonglong2*)&r64[(gr * 4 + jp) * 64 + b0] = v;
    }
}

__device__ __forceinline__ u64 gather16(const u64* r64, int jp, int b)
{
    u64 s0 = r64[(0 * 4 + jp) * 64 + b];
    u64 s1 = r64[(1 * 4 + jp) * 64 + b];
#pragma unroll
    for (int gr = 2; gr < 16; gr += 2) {
        fadd2(s0, r64[(gr * 4 + jp) * 64 + b]);
        fadd2(s1, r64[((gr + 1) * 4 + jp) * 64 + b]);
    }
    fadd2(s0, s1);
    return s0;
}

#define ZERO42(A) do { _Pragma("unroll") for (int _j = 0; _j < 4; _j++) \
    { (A)[_j][0] = 0ULL; (A)[_j][1] = 0ULL; } } while (0)

// ---------------------------------------------------------------------------
// Persistent loop. 128 CTAs x 512 thr; CTA owns j [8*bid, 8*bid+8).
// Warp mapping: bh = warp>>3 (batch half), gw = warp&7; k2 = lane>>4;
// granule gr = gw*2+k2 (16); b0 = bh*32 + (lane&15)*2 (thread: b0, b0+1).
// SMEM floats: wt1[0,8K) Wih1 | wt0[8K,16K) Whh0 | wt2[16K,24K) Whh1 |
//   buf0[24K,40K) | buf1[40K,56K) | bias1[57344?]... see offsets below.
// redA = buf0[0,4096) u64 (32KB), redB = buf0[4096,8192) u64.
// ---------------------------------------------------------------------------
__global__ void __launch_bounds__(NTHR, 1) rnn_persist(
    const float* __restrict__ h0in,
    const float* __restrict__ Whh0, const float* __restrict__ Wih1,
    const float* __restrict__ Whh1, const float* __restrict__ bih1,
    const float* __restrict__ bhh1, float* __restrict__ out)
{
    extern __shared__ float sm[];
    float* wt1  = sm;            // 8192
    float* wt0  = sm + 8192;     // 8192
    float* wt2  = sm + 16384;    // 8192
    float* buf0 = sm + 24576;    // 16384 (64KB)
    float* buf1 = sm + 40960;    // 16384
    float* bias1 = sm + 57344;   // 8
    u64* redA = (u64*)buf0;              // 32KB
    u64* redB = (u64*)(buf0 + 8192);     // 32KB

    const int tid = threadIdx.x;
    const int lane = tid & 31;
    const int warp = tid >> 5;
    const int bh = warp >> 3;
    const int gw = warp & 7;
    const int k2 = lane >> 4;
    const int gr = gw * 2 + k2;
    const int kb = gr * 16;
    const int b0 = bh * 32 + (lane & 15) * 2;
    const int jbase = blockIdx.x * 8;
    const int ejp = tid & 3, eb = tid >> 2;   // valid for tid < 256
    u64 tkt = 0;

    // --- prologue: weights (natural [k][8]) + bias ---
    for (int idx = tid; idx < 8192; idx += NTHR) {
        int jj = idx >> 10, k = idx & 1023;
        wt0[k * 8 + jj] = __ldg(&Whh0[(size_t)(jbase + jj) * 1024 + k]);
        wt1[k * 8 + jj] = __ldg(&Wih1[(size_t)(jbase + jj) * 1024 + k]);
        wt2[k * 8 + jj] = __ldg(&Whh1[(size_t)(jbase + jj) * 1024 + k]);
    }
    if (tid < 8) bias1[tid] = __ldg(&bih1[jbase + tid]) + __ldg(&bhh1[jbase + tid]);

    // --- prologue: transpose h_0 slice ([2][b][k] -> [k][b]) ---
#pragma unroll
    for (int i = 0; i < 2; i++) {
        int idx = tid + i * NTHR;
        int l = idx >> 9, r = idx & 511, k = jbase + (r >> 6), b = r & 63;
        float v = __ldg(&h0in[(size_t)l * 65536 + (size_t)b * 1024 + k]);
        float* dst = l ? g_h1[1] : g_h0[1];
        __stcg(&dst[k * 64 + b], v);
    }
    bar_arrive(tkt);
    bar_wait(tkt);   // transposed h_0 globally visible

    u64 aA[4][2], aB[4][2];

    // --- prologue: H0[0] = tanh(pre[0] + Whh0·H0[-1]) ---
    ZERO42(aB);
    cp_chunk(buf0, g_h0[1]);
    for (int c = 0; c < 4; c++) {
        cp_wait_all();
        __syncthreads();
        if (c < 3) cp_chunk((c & 1) ? buf0 : buf1, g_h0[1] + (size_t)(c + 1) * CK * 64);
        compute_chunk<1>((c & 1) ? buf1 : buf0, wt0 + (size_t)c * CK * 8, wt0, aB, aA, kb, b0);
    }
    stred(redA, aB, gr, b0);   // last compute read buf1; redA (buf0 low) safe
    __syncthreads();
    if (tid < 256) {
        u64 v = gather16(redA, ejp, eb);
        float lo, hi; unpack2(v, lo, hi);
        int j = jbase + ejp * 2;
        const float* pp = g_pre + (size_t)j * 64 + eb;
        __stcg(&g_h0[0][j * 64 + eb], tanhf(lo + __ldcg(pp)));
        __stcg(&g_h0[0][(j + 1) * 64 + eb], tanhf(hi + __ldcg(pp + 64)));
    }
    bar_arrive(tkt);

    // --- main loop: interval t computes H1[t] (aA) and H0[t+1] (aB) ---
    for (int t = 0; t < TT; t++) {
        const int p = t & 1;
        const float* h0src = g_h0[p];
        const float* h1src = g_h1[p ^ 1];

        bar_wait(tkt);   // H0[t], H1[t-1] from all CTAs visible
        cp_chunk(buf0, h0src);

        // prefetch pre[t+1] for epilogue A (independent of barrier data)
        float pf0 = 0.f, pf1 = 0.f;
        if (t < TT - 1 && tid < 256) {
            const float* pp = g_pre + ((size_t)(t + 1) * 1024 + jbase + ejp * 2) * 64 + eb;
            pf0 = __ldcg(pp);
            pf1 = __ldcg(pp + 64);
        }

        ZERO42(aA); ZERO42(aB);
        for (int c = 0; c < 8; c++) {
            cp_wait_all();
            __syncthreads();
            if (c < 7) {
                const float* nsrc = (c + 1 < 4) ? (h0src + (size_t)(c + 1) * CK * 64)
                                                : (h1src + (size_t)(c + 1 - 4) * CK * 64);
                cp_chunk((c & 1) ? buf0 : buf1, nsrc);
            }
            const float* cbuf = (c & 1) ? buf1 : buf0;
            if (c < 4)
                compute_chunk<2>(cbuf, wt1 + (size_t)c * CK * 8, wt0 + (size_t)c * CK * 8,
                                 aA, aB, kb, b0);
            else
                compute_chunk<1>(cbuf, wt2 + (size_t)(c - 4) * CK * 8, wt2, aA, aB, kb, b0);
        }

        // both reductions into buf0 halves (last compute read buf1): single sync
        stred(redA, aA, gr, b0);
        stred(redB, aB, gr, b0);
        __syncthreads();

        if (tid < 256) {
            int j = jbase + ejp * 2;
            // epilogue A: H0[t+1] = tanh(accB + pre[t+1])
            if (t < TT - 1) {
                u64 v = gather16(redB, ejp, eb);
                float lo, hi; unpack2(v, lo, hi);
                __stcg(&g_h0[p ^ 1][j * 64 + eb], tanhf(lo + pf0));
                __stcg(&g_h0[p ^ 1][(j + 1) * 64 + eb], tanhf(hi + pf1));
            }
            // epilogue B: H1[t] = tanh(accA + bias1); write outputs[t]
            u64 v = gather16(redA, ejp, eb);
            float lo, hi; unpack2(v, lo, hi);
            float v0 = tanhf(lo + bias1[ejp * 2]);
            float v1 = tanhf(hi + bias1[ejp * 2 + 1]);
            __stcg(&g_h1[p][j * 64 + eb], v0);
            __stcg(&g_h1[p][(j + 1) * 64 + eb], v1);
            float2 ov; ov.x = v0; ov.y = v1;
            *(float2*)&out[(size_t)t * 65536 + (size_t)eb * 1024 + j] = ov;
        }
        bar_arrive(tkt);
    }
    bar_wait(tkt);   // all final states visible

    // h_n: H0[511] in g_h0[1], H1[511] in g_h1[1]
    for (int e = blockIdx.x * NTHR + tid; e < 2 * BB * HH; e += NCTA * NTHR) {
        int l = e >> 16, r = e & 65535, b = r >> 10, k = r & 1023;
        const float* src = l ? g_h1[1] : g_h0[1];
        out[(size_t)TT * BB * HH + e] = __ldcg(&src[k * 64 + b]);
    }
}

// ---------------------------------------------------------------------------
extern "C" void kernel_launch(void* const* d_in, const int* in_sizes, int n_in,
                              void* d_out, int out_size)
{
    const float* input = (const float*)d_in[0];
    const float* h0in  = (const float*)d_in[1];
    const float* Wih0  = (const float*)d_in[2];
    const float* bih0  = (const float*)d_in[3];
    const float* Whh0  = (const float*)d_in[4];
    const float* bhh0  = (const float*)d_in[5];
    const float* Wih1  = (const float*)d_in[6];
    const float* bih1  = (const float*)d_in[7];
    const float* Whh1  = (const float*)d_in[8];
    const float* bhh1  = (const float*)d_in[9];
    float* out = (float*)d_out;

    const int smem_bytes = (57344 + 8) * 4;  // 229,408 B
    cudaFuncSetAttribute(rnn_persist, cudaFuncAttributeMaxDynamicSharedMemorySize, smem_bytes);

    pregemm<<<dim3(16, 256), 256>>>(input, Wih0, bih0, bhh0);
    rnn_persist<<<NCTA, NTHR, smem_bytes>>>(h0in, Whh0, Wih1, Whh1, bih1, bhh1, out);
}

// round 11
// speedup vs baseline: 1.2819x; 1.1779x over previous
#include <cuda_runtime.h>
#include <math.h>
#include <stdint.h>

#define TT 512
#define BB 64
#define HH 1024
#define NCTA 128
#define NTHR 256

typedef unsigned long long u64;

__device__ __align__(256) float g_pre[(size_t)TT * HH * BB];  // [t][j][b]
__device__ __align__(256) float g_h0[2][HH * BB];             // [k][b]; H0[t] in g_h0[t&1]
__device__ __align__(256) float g_h1[2][HH * BB];             // H1[t] in g_h1[t&1]
__device__ u64 g_arrive;
__device__ volatile u64 g_release;

__device__ __forceinline__ void ffma2(u64& d, u64 a, u64 b)
{ asm("fma.rn.f32x2 %0,%1,%2,%0;" : "+l"(d) : "l"(a), "l"(b)); }
__device__ __forceinline__ void fadd2(u64& d, u64 a)
{ asm("add.rn.f32x2 %0,%0,%1;" : "+l"(d) : "l"(a)); }
__device__ __forceinline__ u64 dup2(float x)
{ u64 r; asm("mov.b64 %0,{%1,%1};" : "=l"(r) : "f"(x)); return r; }
__device__ __forceinline__ void unpack2(u64 s, float& lo, float& hi)
{ asm("mov.b64 {%0,%1},%2;" : "=f"(lo), "=f"(hi) : "l"(s)); }

// Split ticket barrier (monotonic across graph replays; 1 CTA/SM, all resident)
__device__ __forceinline__ void bar_arrive(u64& tkt)
{
    __syncthreads();
    if (threadIdx.x == 0) {
        __threadfence();
        u64 old = atomicAdd(&g_arrive, 1ULL);
        tkt = old / NCTA + 1ULL;
        if ((old % NCTA) == (NCTA - 1)) { __threadfence(); g_release = tkt; }
    }
}
__device__ __forceinline__ void bar_wait(u64 tkt)
{
    if (threadIdx.x == 0) {
        while (g_release < tkt) {}
        __threadfence();
    }
    __syncthreads();
}

// ---------------------------------------------------------------------------
// pregemm (FFMA2): g_pre[t][j][b] = x[t][b]·Wih0[j] + bih0[j] + bhh0[j]
// ---------------------------------------------------------------------------
__global__ void __launch_bounds__(256) pregemm(const float* __restrict__ X,
                                               const float* __restrict__ W,
                                               const float* __restrict__ bih,
                                               const float* __restrict__ bhh)
{
    __shared__ float As[16][132];  // [k][m]
    __shared__ float Bs[16][68];   // [k][n]
    const int tid = threadIdx.x;
    const int m0 = blockIdx.y * 128;
    const int n0 = blockIdx.x * 64;
    const int tx = tid & 15;
    const int ty = tid >> 4;

    u64 acc[4][4];
#pragma unroll
    for (int i = 0; i < 4; i++)
#pragma unroll
        for (int j = 0; j < 4; j++) acc[i][j] = 0ULL;

    for (int k0 = 0; k0 < 1024; k0 += 16) {
#pragma unroll
        for (int i = 0; i < 2; i++) {
            int q = tid + i * 256;
            int m = q >> 2, kq = (q & 3) << 2;
            float4 v = __ldg((const float4*)&X[(size_t)(m0 + m) * 1024 + k0 + kq]);
            As[kq + 0][m] = v.x; As[kq + 1][m] = v.y;
            As[kq + 2][m] = v.z; As[kq + 3][m] = v.w;
        }
        {
            int n = tid >> 2, kq = (tid & 3) << 2;
            float4 v = __ldg((const float4*)&W[(size_t)(n0 + n) * 1024 + k0 + kq]);
            Bs[kq + 0][n] = v.x; Bs[kq + 1][n] = v.y;
            Bs[kq + 2][n] = v.z; Bs[kq + 3][n] = v.w;
        }
        __syncthreads();
#pragma unroll
        for (int kk = 0; kk < 16; kk++) {
            ulonglong2 a01 = *(const ulonglong2*)&As[kk][ty * 8];
            ulonglong2 a23 = *(const ulonglong2*)&As[kk][ty * 8 + 4];
            float4 bv = *(const float4*)&Bs[kk][tx * 4];
            u64 bd0 = dup2(bv.x), bd1 = dup2(bv.y), bd2 = dup2(bv.z), bd3 = dup2(bv.w);
            ffma2(acc[0][0], a01.x, bd0); ffma2(acc[0][1], a01.x, bd1);
            ffma2(acc[0][2], a01.x, bd2); ffma2(acc[0][3], a01.x, bd3);
            ffma2(acc[1][0], a01.y, bd0); ffma2(acc[1][1], a01.y, bd1);
            ffma2(acc[1][2], a01.y, bd2); ffma2(acc[1][3], a01.y, bd3);
            ffma2(acc[2][0], a23.x, bd0); ffma2(acc[2][1], a23.x, bd1);
            ffma2(acc[2][2], a23.x, bd2); ffma2(acc[2][3], a23.x, bd3);
            ffma2(acc[3][0], a23.y, bd0); ffma2(acc[3][1], a23.y, bd1);
            ffma2(acc[3][2], a23.y, bd2); ffma2(acc[3][3], a23.y, bd3);
        }
        __syncthreads();
    }

#pragma unroll
    for (int ip = 0; ip < 4; ip++) {
        int m = m0 + ty * 8 + 2 * ip;
        int t = m >> 6, b = m & 63;
#pragma unroll
        for (int j = 0; j < 4; j++) {
            int gn = n0 + tx * 4 + j;
            u64 bias = dup2(__ldg(&bih[gn]) + __ldg(&bhh[gn]));
            fadd2(acc[ip][j], bias);
            *(u64*)&g_pre[((size_t)t * 1024 + gn) * 64 + b] = acc[ip][j];
        }
    }
}

// ---------------------------------------------------------------------------
// pass: thread covers 64 k-rows (granule), 8 local j (4 u64 pairs) x 4 b.
// h read DIRECTLY from L2 (ld.global.cg), weights from SMEM [k][16].
// ---------------------------------------------------------------------------
template<int NW>
__device__ __forceinline__ void pass(const float* __restrict__ src,
                                     const float* __restrict__ wA,
                                     const float* __restrict__ wB,
                                     u64 (&aA)[4][4], u64 (&aB)[4][4],
                                     int kbase, int hoff, int woff)
{
    for (int blk = 0; blk < 8; blk++) {
#pragma unroll
        for (int ii = 0; ii < 8; ii++) {
            int kl = kbase + blk * 8 + ii;
            float4 h4 = __ldcg((const float4*)(src + (size_t)kl * 64 + hoff));
            u64 hd0 = dup2(h4.x), hd1 = dup2(h4.y), hd2 = dup2(h4.z), hd3 = dup2(h4.w);
            const float* wa = wA + kl * 16 + woff;
            ulonglong2 wa0 = *(const ulonglong2*)wa;
            ulonglong2 wa1 = *(const ulonglong2*)(wa + 4);
            ffma2(aA[0][0], wa0.x, hd0); ffma2(aA[0][1], wa0.x, hd1);
            ffma2(aA[0][2], wa0.x, hd2); ffma2(aA[0][3], wa0.x, hd3);
            ffma2(aA[1][0], wa0.y, hd0); ffma2(aA[1][1], wa0.y, hd1);
            ffma2(aA[1][2], wa0.y, hd2); ffma2(aA[1][3], wa0.y, hd3);
            ffma2(aA[2][0], wa1.x, hd0); ffma2(aA[2][1], wa1.x, hd1);
            ffma2(aA[2][2], wa1.x, hd2); ffma2(aA[2][3], wa1.x, hd3);
            ffma2(aA[3][0], wa1.y, hd0); ffma2(aA[3][1], wa1.y, hd1);
            ffma2(aA[3][2], wa1.y, hd2); ffma2(aA[3][3], wa1.y, hd3);
            if (NW == 2) {
                const float* wb = wB + kl * 16 + woff;
                ulonglong2 wb0 = *(const ulonglong2*)wb;
                ulonglong2 wb1 = *(const ulonglong2*)(wb + 4);
                ffma2(aB[0][0], wb0.x, hd0); ffma2(aB[0][1], wb0.x, hd1);
                ffma2(aB[0][2], wb0.x, hd2); ffma2(aB[0][3], wb0.x, hd3);
                ffma2(aB[1][0], wb0.y, hd0); ffma2(aB[1][1], wb0.y, hd1);
                ffma2(aB[1][2], wb0.y, hd2); ffma2(aB[1][3], wb0.y, hd3);
                ffma2(aB[2][0], wb1.x, hd0); ffma2(aB[2][1], wb1.x, hd1);
                ffma2(aB[2][2], wb1.x, hd2); ffma2(aB[2][3], wb1.x, hd3);
                ffma2(aB[3][0], wb1.y, hd0); ffma2(aB[3][1], wb1.y, hd1);
                ffma2(aB[3][2], wb1.y, hd2); ffma2(aB[3][3], wb1.y, hd3);
            }
        }
    }
}

// Reduction rows padded to 33 u64 to break gather bank conflicts.
__device__ __forceinline__ void stred(u64* red, u64 (&a)[4][4], int gr, int jg, int b0)
{
#pragma unroll
    for (int jp = 0; jp < 4; jp++) {
        int row = gr * 8 + jg * 4 + jp;
#pragma unroll
        for (int bl = 0; bl < 4; bl++)
            red[(size_t)row * 33 + b0 + bl] = a[jp][bl];
    }
}

__device__ __forceinline__ u64 gather16(const u64* red, int jpg, int b)
{
    u64 s0 = red[(size_t)(0 * 8 + jpg) * 33 + b];
    u64 s1 = red[(size_t)(1 * 8 + jpg) * 33 + b];
#pragma unroll
    for (int gr = 2; gr < 16; gr += 2) {
        fadd2(s0, red[(size_t)(gr * 8 + jpg) * 33 + b]);
        fadd2(s1, red[(size_t)((gr + 1) * 8 + jpg) * 33 + b]);
    }
    fadd2(s0, s1);
    return s0;
}

#define ZERO44(A) do { _Pragma("unroll") for (int _j = 0; _j < 4; _j++) \
    _Pragma("unroll") for (int _b = 0; _b < 4; _b++) (A)[_j][_b] = 0ULL; } while (0)

// ---------------------------------------------------------------------------
// Persistent loop. 128 CTAs x 256 thr. CTA = (jt, bh): jt = bid>>1 owns
// j [16*jt, 16*jt+16); bh = bid&1 owns b [32*bh, 32*bh+32).
// SMEM floats: wt1[0,16K) Wih1 | wt0[16K,32K) Whh0 | wt2[32K,48K) Whh1
//   (each [k][16]) | red u64[128][33] at 49152 | bias1[57600,+16)
// Total 230,464 B.
// ---------------------------------------------------------------------------
__global__ void __launch_bounds__(NTHR, 1) rnn_persist(
    const float* __restrict__ h0in,
    const float* __restrict__ Whh0, const float* __restrict__ Wih1,
    const float* __restrict__ Whh1, const float* __restrict__ bih1,
    const float* __restrict__ bhh1, float* __restrict__ out)
{
    extern __shared__ float sm[];
    float* wt1 = sm;             // 16384 floats
    float* wt0 = sm + 16384;
    float* wt2 = sm + 32768;
    u64*   red = (u64*)(sm + 49152);   // 128 rows x 33 u64
    float* bias1 = sm + 57600;         // 16

    const int tid  = threadIdx.x;
    const int lane = tid & 31;
    const int warp = tid >> 5;
    const int k2   = lane >> 4;
    const int gr   = warp * 2 + k2;       // granule 0..15
    const int kbase = gr * 64;
    const int jg   = (lane >> 3) & 1;     // j-group (8 j each)
    const int woff = jg * 8;
    const int b0   = (lane & 7) * 4;      // local b 0..28
    const int jt   = blockIdx.x >> 1;
    const int bh   = blockIdx.x & 1;
    const int jbase = jt * 16;
    const int hoff  = bh * 32 + b0;
    // epilogue mapping: 256 outputs = 8 j-pairs x 32 b
    const int ejp = tid & 7;              // j-pair 0..7 (local j = 2*ejp)
    const int ebl = tid >> 3;             // local b 0..31
    const int ej  = jbase + ejp * 2;
    const int ebg = bh * 32 + ebl;
    u64 tkt = 0;

    // --- prologue: weight slices [k][16] + bias ---
    for (int idx = tid; idx < 16384; idx += NTHR) {
        int jj = idx >> 10, k = idx & 1023;
        wt0[k * 16 + jj] = __ldg(&Whh0[(size_t)(jbase + jj) * 1024 + k]);
        wt1[k * 16 + jj] = __ldg(&Wih1[(size_t)(jbase + jj) * 1024 + k]);
        wt2[k * 16 + jj] = __ldg(&Whh1[(size_t)(jbase + jj) * 1024 + k]);
    }
    if (tid < 16) bias1[tid] = __ldg(&bih1[jbase + tid]) + __ldg(&bhh1[jbase + tid]);

    // --- prologue: transpose h_0 slice (16 k x 32 b x 2 layers = 1024) ---
#pragma unroll
    for (int i = 0; i < 4; i++) {
        int idx = tid + i * NTHR;
        int l = idx >> 9, r = idx & 511;
        int k = jbase + (r >> 5), b = bh * 32 + (r & 31);
        float v = __ldg(&h0in[(size_t)l * 65536 + (size_t)b * 1024 + k]);
        float* dst = l ? g_h1[1] : g_h0[1];
        __stcg(&dst[k * 64 + b], v);
    }
    bar_arrive(tkt);
    bar_wait(tkt);   // init state globally visible

    u64 aA[4][4], aB[4][4];

    // --- prologue: H0[0] = tanh(pre[0] + Whh0·H0[-1]) ---
    ZERO44(aB);
    pass<1>(g_h0[1], wt0, wt0, aB, aA, kbase, hoff, woff);
    stred(red, aB, gr, jg, b0);
    __syncthreads();
    {
        u64 v = gather16(red, ejp, ebl);
        float lo, hi; unpack2(v, lo, hi);
        const float* pp = g_pre + (size_t)ej * 64 + ebg;
        __stcg(&g_h0[0][ej * 64 + ebg], tanhf(lo + __ldcg(pp)));
        __stcg(&g_h0[0][(ej + 1) * 64 + ebg], tanhf(hi + __ldcg(pp + 64)));
    }
    bar_arrive(tkt);

    // --- main loop: interval t computes H1[t] (aA) and H0[t+1] (aB) ---
    for (int t = 0; t < TT; t++) {
        const int p = t & 1;

        // prefetch pre[t+1] while other CTAs reach the barrier
        float pf0 = 0.f, pf1 = 0.f;
        if (t < TT - 1) {
            const float* pp = g_pre + ((size_t)(t + 1) * 1024 + ej) * 64 + ebg;
            pf0 = __ldcg(pp);
            pf1 = __ldcg(pp + 64);
        }
        bar_wait(tkt);   // H0[t], H1[t-1] from all CTAs visible

        ZERO44(aA); ZERO44(aB);
        pass<2>(g_h0[p], wt1, wt0, aA, aB, kbase, hoff, woff);      // Wih1->aA, Whh0->aB
        pass<1>(g_h1[p ^ 1], wt2, wt2, aA, aB, kbase, hoff, woff);  // Whh1->aA

        // round 1: H1[t] from aA
        __syncthreads();   // prior gather reads done (from last step's round 2)
        stred(red, aA, gr, jg, b0);
        __syncthreads();
        {
            u64 v = gather16(red, ejp, ebl);
            float lo, hi; unpack2(v, lo, hi);
            float v0 = tanhf(lo + bias1[ejp * 2]);
            float v1 = tanhf(hi + bias1[ejp * 2 + 1]);
            __stcg(&g_h1[p][ej * 64 + ebg], v0);
            __stcg(&g_h1[p][(ej + 1) * 64 + ebg], v1);
            float2 ov; ov.x = v0; ov.y = v1;
            *(float2*)&out[(size_t)t * 65536 + (size_t)ebg * 1024 + ej] = ov;
        }

        // round 2: H0[t+1] from aB
        if (t < TT - 1) {
            __syncthreads();
            stred(red, aB, gr, jg, b0);
            __syncthreads();
            u64 v = gather16(red, ejp, ebl);
            float lo, hi; unpack2(v, lo, hi);
            __stcg(&g_h0[p ^ 1][ej * 64 + ebg], tanhf(lo + pf0));
            __stcg(&g_h0[p ^ 1][(ej + 1) * 64 + ebg], tanhf(hi + pf1));
        }
        bar_arrive(tkt);   // includes __syncthreads (protects red for next step)
    }
    bar_wait(tkt);   // all final states visible

    // h_n: H0[511] in g_h0[1], H1[511] in g_h1[1]
    for (int e = blockIdx.x * NTHR + tid; e < 2 * BB * HH; e += NCTA * NTHR) {
        int l = e >> 16, r = e & 65535, b = r >> 10, k = r & 1023;
        const float* src = l ? g_h1[1] : g_h0[1];
        out[(size_t)TT * BB * HH + e] = __ldcg(&src[k * 64 + b]);
    }
}

// ---------------------------------------------------------------------------
extern "C" void kernel_launch(void* const* d_in, const int* in_sizes, int n_in,
                              void* d_out, int out_size)
{
    const float* input = (const float*)d_in[0];
    const float* h0in  = (const float*)d_in[1];
    const float* Wih0  = (const float*)d_in[2];
    const float* bih0  = (const float*)d_in[3];
    const float* Whh0  = (const float*)d_in[4];
    const float* bhh0  = (const float*)d_in[5];
    const float* Wih1  = (const float*)d_in[6];
    const float* bih1  = (const float*)d_in[7];
    const float* Whh1  = (const float*)d_in[8];
    const float* bhh1  = (const float*)d_in[9];
    float* out = (float*)d_out;

    const int smem_bytes = 230464;
    cudaFuncSetAttribute(rnn_persist, cudaFuncAttributeMaxDynamicSharedMemorySize, smem_bytes);

    pregemm<<<dim3(16, 256), 256>>>(input, Wih0, bih0, bhh0);
    rnn_persist<<<NCTA, NTHR, smem_bytes>>>(h0in, Whh0, Wih1, Whh1, bih1, bhh1, out);
}

// round 14
// speedup vs baseline: 1.3397x; 1.0451x over previous
#include <cuda_runtime.h>
#include <math.h>
#include <stdint.h>

#define TT 512
#define BB 64
#define HH 1024
#define NCTA 128
#define NTHR 512

typedef unsigned long long u64;

__device__ __align__(256) float g_pre[(size_t)TT * HH * BB];  // [t][j][b]
__device__ __align__(256) float g_h0[2][HH * BB];             // [k][b]; H0[t] in g_h0[t&1]
__device__ __align__(256) float g_h1[2][HH * BB];             // H1[t] in g_h1[t&1]
__device__ u64 g_arrive;
__device__ volatile u64 g_release;

__device__ __forceinline__ void ffma2(u64& d, u64 a, u64 b)
{ asm("fma.rn.f32x2 %0,%1,%2,%0;" : "+l"(d) : "l"(a), "l"(b)); }
__device__ __forceinline__ void fadd2(u64& d, u64 a)
{ asm("add.rn.f32x2 %0,%0,%1;" : "+l"(d) : "l"(a)); }
__device__ __forceinline__ u64 dup2(float x)
{ u64 r; asm("mov.b64 %0,{%1,%1};" : "=l"(r) : "f"(x)); return r; }
__device__ __forceinline__ void unpack2(u64 s, float& lo, float& hi)
{ asm("mov.b64 {%0,%1},%2;" : "=f"(lo), "=f"(hi) : "l"(s)); }

// Split ticket barrier (monotonic across graph replays; 1 CTA/SM, all resident)
__device__ __forceinline__ void bar_arrive(u64& tkt)
{
    __syncthreads();
    if (threadIdx.x == 0) {
        __threadfence();
        u64 old = atomicAdd(&g_arrive, 1ULL);
        tkt = old / NCTA + 1ULL;
        if ((old % NCTA) == (NCTA - 1)) { __threadfence(); g_release = tkt; }
    }
}
__device__ __forceinline__ void bar_wait(u64 tkt)
{
    if (threadIdx.x == 0) {
        while (g_release < tkt) {}
        __threadfence();
    }
    __syncthreads();
}

// ---------------------------------------------------------------------------
// pregemm (FFMA2): g_pre[t][j][b] = x[t][b]·Wih0[j] + bih0[j] + bhh0[j]
// ---------------------------------------------------------------------------
__global__ void __launch_bounds__(256) pregemm(const float* __restrict__ X,
                                               const float* __restrict__ W,
                                               const float* __restrict__ bih,
                                               const float* __restrict__ bhh)
{
    __shared__ float As[16][132];  // [k][m]
    __shared__ float Bs[16][68];   // [k][n]
    const int tid = threadIdx.x;
    const int m0 = blockIdx.y * 128;
    const int n0 = blockIdx.x * 64;
    const int tx = tid & 15;
    const int ty = tid >> 4;

    u64 acc[4][4];
#pragma unroll
    for (int i = 0; i < 4; i++)
#pragma unroll
        for (int j = 0; j < 4; j++) acc[i][j] = 0ULL;

    for (int k0 = 0; k0 < 1024; k0 += 16) {
#pragma unroll
        for (int i = 0; i < 2; i++) {
            int q = tid + i * 256;
            int m = q >> 2, kq = (q & 3) << 2;
            float4 v = __ldg((const float4*)&X[(size_t)(m0 + m) * 1024 + k0 + kq]);
            As[kq + 0][m] = v.x; As[kq + 1][m] = v.y;
            As[kq + 2][m] = v.z; As[kq + 3][m] = v.w;
        }
        {
            int n = tid >> 2, kq = (tid & 3) << 2;
            float4 v = __ldg((const float4*)&W[(size_t)(n0 + n) * 1024 + k0 + kq]);
            Bs[kq + 0][n] = v.x; Bs[kq + 1][n] = v.y;
            Bs[kq + 2][n] = v.z; Bs[kq + 3][n] = v.w;
        }
        __syncthreads();
#pragma unroll
        for (int kk = 0; kk < 16; kk++) {
            ulonglong2 a01 = *(const ulonglong2*)&As[kk][ty * 8];
            ulonglong2 a23 = *(const ulonglong2*)&As[kk][ty * 8 + 4];
            float4 bv = *(const float4*)&Bs[kk][tx * 4];
            u64 bd0 = dup2(bv.x), bd1 = dup2(bv.y), bd2 = dup2(bv.z), bd3 = dup2(bv.w);
            ffma2(acc[0][0], a01.x, bd0); ffma2(acc[0][1], a01.x, bd1);
            ffma2(acc[0][2], a01.x, bd2); ffma2(acc[0][3], a01.x, bd3);
            ffma2(acc[1][0], a01.y, bd0); ffma2(acc[1][1], a01.y, bd1);
            ffma2(acc[1][2], a01.y, bd2); ffma2(acc[1][3], a01.y, bd3);
            ffma2(acc[2][0], a23.x, bd0); ffma2(acc[2][1], a23.x, bd1);
            ffma2(acc[2][2], a23.x, bd2); ffma2(acc[2][3], a23.x, bd3);
            ffma2(acc[3][0], a23.y, bd0); ffma2(acc[3][1], a23.y, bd1);
            ffma2(acc[3][2], a23.y, bd2); ffma2(acc[3][3], a23.y, bd3);
        }
        __syncthreads();
    }

#pragma unroll
    for (int ip = 0; ip < 4; ip++) {
        int m = m0 + ty * 8 + 2 * ip;
        int t = m >> 6, b = m & 63;
#pragma unroll
        for (int j = 0; j < 4; j++) {
            int gn = n0 + tx * 4 + j;
            u64 bias = dup2(__ldg(&bih[gn]) + __ldg(&bhh[gn]));
            fadd2(acc[ip][j], bias);
            *(u64*)&g_pre[((size_t)t * 1024 + gn) * 64 + b] = acc[ip][j];
        }
    }
}

// ---------------------------------------------------------------------------
// pass: thread covers 32 k-rows, 8 local j (4 u64 pairs) x 4 b.
// h read directly from L2 (ld.global.cg), weights from SMEM [k][16].
// ---------------------------------------------------------------------------
template<int NW>
__device__ __forceinline__ void pass(const float* __restrict__ src,
                                     const float* __restrict__ wA,
                                     const float* __restrict__ wB,
                                     u64 (&aA)[4][4], u64 (&aB)[4][4],
                                     int kbase, int hoff, int woff)
{
    for (int blk = 0; blk < 4; blk++) {
#pragma unroll
        for (int ii = 0; ii < 8; ii++) {
            int kl = kbase + blk * 8 + ii;
            float4 h4 = __ldcg((const float4*)(src + (size_t)kl * 64 + hoff));
            u64 hd0 = dup2(h4.x), hd1 = dup2(h4.y), hd2 = dup2(h4.z), hd3 = dup2(h4.w);
            const float* wa = wA + kl * 16 + woff;
            ulonglong2 wa0 = *(const ulonglong2*)wa;
            ulonglong2 wa1 = *(const ulonglong2*)(wa + 4);
            ffma2(aA[0][0], wa0.x, hd0); ffma2(aA[0][1], wa0.x, hd1);
            ffma2(aA[0][2], wa0.x, hd2); ffma2(aA[0][3], wa0.x, hd3);
            ffma2(aA[1][0], wa0.y, hd0); ffma2(aA[1][1], wa0.y, hd1);
            ffma2(aA[1][2], wa0.y, hd2); ffma2(aA[1][3], wa0.y, hd3);
            ffma2(aA[2][0], wa1.x, hd0); ffma2(aA[2][1], wa1.x, hd1);
            ffma2(aA[2][2], wa1.x, hd2); ffma2(aA[2][3], wa1.x, hd3);
            ffma2(aA[3][0], wa1.y, hd0); ffma2(aA[3][1], wa1.y, hd1);
            ffma2(aA[3][2], wa1.y, hd2); ffma2(aA[3][3], wa1.y, hd3);
            if (NW == 2) {
                const float* wb = wB + kl * 16 + woff;
                ulonglong2 wb0 = *(const ulonglong2*)wb;
                ulonglong2 wb1 = *(const ulonglong2*)(wb + 4);
                ffma2(aB[0][0], wb0.x, hd0); ffma2(aB[0][1], wb0.x, hd1);
                ffma2(aB[0][2], wb0.x, hd2); ffma2(aB[0][3], wb0.x, hd3);
                ffma2(aB[1][0], wb0.y, hd0); ffma2(aB[1][1], wb0.y, hd1);
                ffma2(aB[1][2], wb0.y, hd2); ffma2(aB[1][3], wb0.y, hd3);
                ffma2(aB[2][0], wb1.x, hd0); ffma2(aB[2][1], wb1.x, hd1);
                ffma2(aB[2][2], wb1.x, hd2); ffma2(aB[2][3], wb1.x, hd3);
                ffma2(aB[3][0], wb1.y, hd0); ffma2(aB[3][1], wb1.y, hd1);
                ffma2(aB[3][2], wb1.y, hd2); ffma2(aB[3][3], wb1.y, hd3);
            }
        }
    }
}

// In-warp combine of the two k2 half-granules: lane L and L^16 hold the same
// (j,b) sub-tile for adjacent 32-row k-granules.
__device__ __forceinline__ void comb(u64 (&a)[4][4])
{
#pragma unroll
    for (int jp = 0; jp < 4; jp++)
#pragma unroll
        for (int bl = 0; bl < 4; bl++) {
            u64 o = __shfl_xor_sync(0xffffffffu, a[jp][bl], 16);
            fadd2(a[jp][bl], o);
        }
}

// Reduction rows padded to 33 u64 to break gather bank conflicts.
__device__ __forceinline__ void stred(u64* red, u64 (&a)[4][4], int gr, int jg, int b0)
{
#pragma unroll
    for (int jp = 0; jp < 4; jp++) {
        int row = gr * 8 + jg * 4 + jp;
#pragma unroll
        for (int bl = 0; bl < 4; bl++)
            red[(size_t)row * 33 + b0 + bl] = a[jp][bl];
    }
}

__device__ __forceinline__ u64 gather16(const u64* red, int jpg, int b)
{
    u64 s0 = red[(size_t)(0 * 8 + jpg) * 33 + b];
    u64 s1 = red[(size_t)(1 * 8 + jpg) * 33 + b];
#pragma unroll
    for (int gr = 2; gr < 16; gr += 2) {
        fadd2(s0, red[(size_t)(gr * 8 + jpg) * 33 + b]);
        fadd2(s1, red[(size_t)((gr + 1) * 8 + jpg) * 33 + b]);
    }
    fadd2(s0, s1);
    return s0;
}

#define ZERO44(A) do { _Pragma("unroll") for (int _j = 0; _j < 4; _j++) \
    _Pragma("unroll") for (int _b = 0; _b < 4; _b++) (A)[_j][_b] = 0ULL; } while (0)

// ---------------------------------------------------------------------------
// Persistent loop. 128 CTAs x 512 thr. CTA = (jt, bh): jt = bid>>1 owns
// j [16*jt, 16*jt+16); bh = bid&1 owns b [32*bh, 32*bh+32).
// Warp w owns k [64w, 64w+64); half-warp k2 covers 32 rows; shuffle-combined
// granule = warp id (16 granules).
// SMEM floats: wt1[0,16K) Wih1 | wt0[16K,32K) Whh0 | wt2[32K,48K) Whh1
//   | red u64[128][33] at 49152 | bias1[57600,+16)   (230,464 B)
// ---------------------------------------------------------------------------
__global__ void __launch_bounds__(NTHR, 1) rnn_persist(
    const float* __restrict__ h0in,
    const float* __restrict__ Whh0, const float* __restrict__ Wih1,
    const float* __restrict__ Whh1, const float* __restrict__ bih1,
    const float* __restrict__ bhh1, float* __restrict__ out)
{
    extern __shared__ float sm[];
    float* wt1 = sm;             // 16384 floats
    float* wt0 = sm + 16384;
    float* wt2 = sm + 32768;
    u64*   red = (u64*)(sm + 49152);   // 128 rows x 33 u64
    float* bias1 = sm + 57600;         // 16

    const int tid  = threadIdx.x;
    const int lane = tid & 31;
    const int warp = tid >> 5;
    const int k2   = lane >> 4;
    const int kbase = warp * 64 + k2 * 32;
    const int jg   = (lane >> 3) & 1;     // j-group (8 j each)
    const int woff = jg * 8;
    const int b0   = (lane & 7) * 4;      // local b 0..28
    const int jt   = blockIdx.x >> 1;
    const int bh   = blockIdx.x & 1;
    const int jbase = jt * 16;
    const int hoff  = bh * 32 + b0;
    // epilogue mapping (tid < 256): 8 j-pairs x 32 b
    const int ejp = tid & 7;
    const int ebl = (tid >> 3) & 31;
    const int ej  = jbase + ejp * 2;
    const int ebg = bh * 32 + ebl;
    u64 tkt = 0;

    // --- prologue: weight slices [k][16] + bias ---
    for (int idx = tid; idx < 16384; idx += NTHR) {
        int jj = idx >> 10, k = idx & 1023;
        wt0[k * 16 + jj] = __ldg(&Whh0[(size_t)(jbase + jj) * 1024 + k]);
        wt1[k * 16 + jj] = __ldg(&Wih1[(size_t)(jbase + jj) * 1024 + k]);
        wt2[k * 16 + jj] = __ldg(&Whh1[(size_t)(jbase + jj) * 1024 + k]);
    }
    if (tid < 16) bias1[tid] = __ldg(&bih1[jbase + tid]) + __ldg(&bhh1[jbase + tid]);

    // --- prologue: transpose h_0 slice (16 k x 32 b x 2 layers = 1024) ---
#pragma unroll
    for (int i = 0; i < 2; i++) {
        int idx = tid + i * NTHR;
        int l = idx >> 9, r = idx & 511;
        int k = jbase + (r >> 5), b = bh * 32 + (r & 31);
        float v = __ldg(&h0in[(size_t)l * 65536 + (size_t)b * 1024 + k]);
        float* dst = l ? g_h1[1] : g_h0[1];
        __stcg(&dst[k * 64 + b], v);
    }
    bar_arrive(tkt);
    bar_wait(tkt);   // init state globally visible

    u64 aA[4][4], aB[4][4];

    // --- prologue: H0[0] = tanh(pre[0] + Whh0·H0[-1]) ---
    ZERO44(aB);
    pass<1>(g_h0[1], wt0, wt0, aB, aA, kbase, hoff, woff);
    comb(aB);
    if (lane < 16) stred(red, aB, warp, jg, b0);
    __syncthreads();
    if (tid < 256) {
        u64 v = gather16(red, ejp, ebl);
        float lo, hi; unpack2(v, lo, hi);
        const float* pp = g_pre + (size_t)ej * 64 + ebg;
        __stcg(&g_h0[0][ej * 64 + ebg], tanhf(lo + __ldcg(pp)));
        __stcg(&g_h0[0][(ej + 1) * 64 + ebg], tanhf(hi + __ldcg(pp + 64)));
    }
    bar_arrive(tkt);

    // --- main loop: interval t computes H1[t] (aA) and H0[t+1] (aB) ---
    for (int t = 0; t < TT; t++) {
        const int p = t & 1;

        // prefetch pre[t+1] while other CTAs reach the barrier
        float pf0 = 0.f, pf1 = 0.f;
        if (t < TT - 1 && tid < 256) {
            const float* pp = g_pre + ((size_t)(t + 1) * 1024 + ej) * 64 + ebg;
            pf0 = __ldcg(pp);
            pf1 = __ldcg(pp + 64);
        }
        bar_wait(tkt);   // H0[t], H1[t-1] from all CTAs visible

        ZERO44(aA); ZERO44(aB);
        pass<2>(g_h0[p], wt1, wt0, aA, aB, kbase, hoff, woff);      // Wih1->aA, Whh0->aB
        pass<1>(g_h1[p ^ 1], wt2, wt2, aA, aB, kbase, hoff, woff);  // Whh1->aA
        comb(aA);
        comb(aB);

        // round 1: H1[t] from aA
        __syncthreads();   // prior gather reads of red are done
        if (lane < 16) stred(red, aA, warp, jg, b0);
        __syncthreads();
        if (tid < 256) {
            u64 v = gather16(red, ejp, ebl);
            float lo, hi; unpack2(v, lo, hi);
            float v0 = tanhf(lo + bias1[ejp * 2]);
            float v1 = tanhf(hi + bias1[ejp * 2 + 1]);
            __stcg(&g_h1[p][ej * 64 + ebg], v0);
            __stcg(&g_h1[p][(ej + 1) * 64 + ebg], v1);
            float2 ov; ov.x = v0; ov.y = v1;
            *(float2*)&out[(size_t)t * 65536 + (size_t)ebg * 1024 + ej] = ov;
        }

        // round 2: H0[t+1] from aB
        if (t < TT - 1) {
            __syncthreads();
            if (lane < 16) stred(red, aB, warp, jg, b0);
            __syncthreads();
            if (tid < 256) {
                u64 v = gather16(red, ejp, ebl);
                float lo, hi; unpack2(v, lo, hi);
                __stcg(&g_h0[p ^ 1][ej * 64 + ebg], tanhf(lo + pf0));
                __stcg(&g_h0[p ^ 1][(ej + 1) * 64 + ebg], tanhf(hi + pf1));
            }
        }
        bar_arrive(tkt);   // includes __syncthreads (protects red for next step)
    }
    bar_wait(tkt);   // all final states visible

    // h_n: H0[511] in g_h0[1], H1[511] in g_h1[1]
    for (int e = blockIdx.x * NTHR + tid; e < 2 * BB * HH; e += NCTA * NTHR) {
        int l = e >> 16, r = e & 65535, b = r >> 10, k = r & 1023;
        const float* src = l ? g_h1[1] : g_h0[1];
        out[(size_t)TT * BB * HH + e] = __ldcg(&src[k * 64 + b]);
    }
}

// ---------------------------------------------------------------------------
extern "C" void kernel_launch(void* const* d_in, const int* in_sizes, int n_in,
                              void* d_out, int out_size)
{
    const float* input = (const float*)d_in[0];
    const float* h0in  = (const float*)d_in[1];
    const float* Wih0  = (const float*)d_in[2];
    const float* bih0  = (const float*)d_in[3];
    const float* Whh0  = (const float*)d_in[4];
    const float* bhh0  = (const float*)d_in[5];
    const float* Wih1  = (const float*)d_in[6];
    const float* bih1  = (const float*)d_in[7];
    const float* Whh1  = (const float*)d_in[8];
    const float* bhh1  = (const float*)d_in[9];
    float* out = (float*)d_out;

    const int smem_bytes = 230464;
    cudaFuncSetAttribute(rnn_persist, cudaFuncAttributeMaxDynamicSharedMemorySize, smem_bytes);

    pregemm<<<dim3(16, 256), 256>>>(input, Wih0, bih0, bhh0);
    rnn_persist<<<NCTA, NTHR, smem_bytes>>>(h0in, Whh0, Wih1, Whh1, bih1, bhh1, out);
}